// round 4
// baseline (speedup 1.0000x reference)
#include <cuda_runtime.h>
#include <math.h>

// Warp-parallel computation of M (3x3) such that
//   z = (1, cos x0, sin x0) . M . (1, cos x1, sin x1)^T
// equals psi^T S psi with S = Re(U^dag (Z(x)I) U) for the pair-0 2-qubit circuit.
// Lane layout: lane = r*4 + c holds U[r][c] (complex, as ux/uy).
// Lanes 16..31 hold a harmless replica (r,c wrap).
__device__ __forceinline__ void compute_M_warp(
    const float* __restrict__ params, float* __restrict__ sS, float* __restrict__ sM)
{
    const unsigned FULL = 0xffffffffu;
    int lane = threadIdx.x & 31;
    int r = (lane >> 2) & 3;
    int c = lane & 3;
    bool rb0 = (r & 1) != 0;        // qubit B bit
    bool rb1 = ((r >> 1) & 1) != 0; // qubit A bit

    float ux = (r == c) ? 1.0f : 0.0f;  // U = identity
    float uy = 0.0f;

#pragma unroll
    for (int layer = 0; layer < 3; layer++) {
        float t0 = __ldg(params + layer * 16 + 0);
        float t1 = __ldg(params + layer * 16 + 1);
        float t2 = __ldg(params + layer * 16 + 2);
        float t3 = __ldg(params + layer * 16 + 3);
        float ch, sh;

        // RZ(t0) on qubit A: row phase e^{-i t/2} (bit=0) or e^{+i t/2} (bit=1)
        __sincosf(0.5f * t0, &sh, &ch);
        {
            float py = rb1 ? sh : -sh;
            float nx = ch * ux - py * uy;
            float ny = fmaf(ch, uy, py * ux);
            ux = nx; uy = ny;
        }
        // RX(t1) on qubit B: u = ch*u + (-i sh)*partner,  partner row = r^1
        __sincosf(0.5f * t1, &sh, &ch);
        {
            float px = __shfl_xor_sync(FULL, ux, 4);
            float py = __shfl_xor_sync(FULL, uy, 4);
            float nx = fmaf(ch, ux,  sh * py);
            float ny = fmaf(ch, uy, -sh * px);
            ux = nx; uy = ny;
        }
        // CNOT(A->B): swap rows 2 and 3 (rows with A-bit set exchange B-bit)
        {
            float px = __shfl_xor_sync(FULL, ux, 4);
            float py = __shfl_xor_sync(FULL, uy, 4);
            if (rb1) { ux = px; uy = py; }
        }
        // RZ(t2) on qubit B
        __sincosf(0.5f * t2, &sh, &ch);
        {
            float py = rb0 ? sh : -sh;
            float nx = ch * ux - py * uy;
            float ny = fmaf(ch, uy, py * ux);
            ux = nx; uy = ny;
        }
        // RX(t3) on qubit B
        __sincosf(0.5f * t3, &sh, &ch);
        {
            float px = __shfl_xor_sync(FULL, ux, 4);
            float py = __shfl_xor_sync(FULL, uy, 4);
            float nx = fmaf(ch, ux,  sh * py);
            float ny = fmaf(ch, uy, -sh * px);
            ux = nx; uy = ny;
        }
    }

    // S[k][l] = sum_m z_m * Re(conj(U[m][k]) * U[m][l]),  z = (+1,+1,-1,-1)
    // lane = k*4 + l computes one entry (k=r, l=c).
    {
        float acc = 0.0f;
#pragma unroll
        for (int m = 0; m < 4; m++) {
            float ax = __shfl_sync(FULL, ux, m * 4 + r);
            float ay = __shfl_sync(FULL, uy, m * 4 + r);
            float bx = __shfl_sync(FULL, ux, m * 4 + c);
            float by = __shfl_sync(FULL, uy, m * 4 + c);
            float term = fmaf(ax, bx, ay * by);
            acc += (m < 2) ? term : -term;
        }
        if (lane < 16) sS[lane] = acc;
        __syncwarp();
    }

    // Fold S (half-angle quadratic form) into M (full-angle bilinear form):
    // cos^2(x/2)=(1+C)/2, sin^2=(1-C)/2, cos*sin=S/2.
    if (lane == 0) {
        const float E[2][2][3] = {
            { {0.5f, 0.5f, 0.0f}, {0.0f, 0.0f, 0.5f} },
            { {0.0f, 0.0f, 0.5f}, {0.5f, -0.5f, 0.0f} }
        };
#pragma unroll
        for (int u = 0; u < 3; u++)
#pragma unroll
            for (int v = 0; v < 3; v++) {
                float acc = 0.0f;
#pragma unroll
                for (int a = 0; a < 2; a++)
#pragma unroll
                    for (int cc = 0; cc < 2; cc++) {
                        float ea = E[a][cc][u];
                        if (ea == 0.0f) continue;
#pragma unroll
                        for (int b = 0; b < 2; b++)
#pragma unroll
                            for (int d = 0; d < 2; d++) {
                                float eb = E[b][d][v];
                                if (eb == 0.0f) continue;
                                acc = fmaf(sS[(2 * a + b) * 4 + (2 * cc + d)], ea * eb, acc);
                            }
                    }
                sM[u * 3 + v] = acc;
            }
    }
}

__device__ __forceinline__ float eval_elem(const float* sM, float x0, float x1) {
    float C0, S0, C1, S1;
    __sincosf(x0, &S0, &C0);
    __sincosf(x1, &S1, &C1);
    float t0 = fmaf(sM[2], S1, fmaf(sM[1], C1, sM[0]));
    float t1 = fmaf(sM[5], S1, fmaf(sM[4], C1, sM[3]));
    float t2 = fmaf(sM[8], S1, fmaf(sM[7], C1, sM[6]));
    float z  = fmaf(t2, S0, fmaf(t1, C0, t0));
    return __fdividef(1.0f, 1.0f + __expf(-z));
}

__global__ void __launch_bounds__(128, 8) qcnn_kernel(
    const float* __restrict__ inputs,   // (B, 8) row-major
    const float* __restrict__ params,   // (48,)
    float* __restrict__ out,            // (B,)
    int n)
{
    __shared__ float sS[16];
    __shared__ float sM[9];

    int t = blockIdx.x * blockDim.x + threadIdx.x;
    int b0 = t * 2;

    // Front-batch both independent loads BEFORE the prologue so DRAM latency
    // overlaps the warp-parallel compute_M.
    const float4* in4 = reinterpret_cast<const float4*>(inputs);
    float4 e0 = make_float4(0.f, 0.f, 0.f, 0.f);
    float4 e1 = e0;
    bool valid = (b0 + 1) < n;
    if (valid) {
        e0 = __ldg(in4 + 2 * b0);       // element b0:  x0=.x, x1=.y
        e1 = __ldg(in4 + 2 * b0 + 2);   // element b0+1
    }

    if (threadIdx.x < 32) {
        compute_M_warp(params, sS, sM);
    }
    __syncthreads();

    if (!valid) return;

    float r0 = eval_elem(sM, e0.x, e0.y);
    float r1 = eval_elem(sM, e1.x, e1.y);

    reinterpret_cast<float2*>(out)[t] = make_float2(r0, r1);
}

extern "C" void kernel_launch(void* const* d_in, const int* in_sizes, int n_in,
                              void* d_out, int out_size) {
    const float* inputs = (const float*)d_in[0];
    const float* params = (const float*)d_in[1];
    float* out = (float*)d_out;

    int n = out_size;  // 131072
    int threads = 128;
    int elems_per_block = threads * 2;
    int blocks = (n + elems_per_block - 1) / elems_per_block;  // 512
    qcnn_kernel<<<blocks, threads>>>(inputs, params, out, n);
}